// round 3
// baseline (speedup 1.0000x reference)
#include <cuda_runtime.h>
#include <math.h>

// ---------------- problem constants ----------------
#define TOK   4096          // B*S = 4*1024
#define SEQ   1024
#define BATCH 4
#define EMB   512
#define NH    8
#define HD    64
#define NEXP  32
#define TOPK  4
#define RRANK 64
#define SHID  4096
#define EHID  512

// ---------------- device scratch (static, allocation-free) ----------------
__device__ float g_h1[TOK * EMB];
__device__ float g_q[TOK * EMB];
__device__ float g_k[TOK * EMB];
__device__ float g_v[TOK * EMB];
__device__ float g_attn[TOK * EMB];
__device__ float g_x1[TOK * EMB];
__device__ float g_h2[TOK * EMB];
__device__ float g_rlat[TOK * RRANK];
__device__ float g_logits[TOK * NEXP];
__device__ int   g_topi[TOK * TOPK];
__device__ float g_topw[TOK * TOPK];
__device__ float g_imp[NEXP];
__device__ int   g_cnt[NEXP];
__device__ int   g_off[NEXP];
__device__ int   g_cur[NEXP];
__device__ int   g_atok[TOK * TOPK];
__device__ float g_aw[TOK * TOPK];
__device__ float g_H[TOK * TOPK * EHID];   // routed hidden, 33.5 MB
__device__ float g_hs[TOK * SHID];         // shared-expert hidden, 67 MB

// ---------------- helpers ----------------
__device__ __forceinline__ float gelu_tanh(float x) {
    float x3 = x * x * x;
    return 0.5f * x * (1.0f + tanhf(0.7978845608028654f * (x + 0.044715f * x3)));
}

// ---------------- LayerNorm: one block per token ----------------
__global__ __launch_bounds__(128) void ln_kernel(const float* __restrict__ X,
                                                 const float* __restrict__ g,
                                                 const float* __restrict__ b,
                                                 float* __restrict__ Y) {
    int t = blockIdx.x;
    int tid = threadIdx.x;               // 128 threads, 4 floats each
    const float4 v = *reinterpret_cast<const float4*>(X + (size_t)t * EMB + tid * 4);
    float s  = v.x + v.y + v.z + v.w;
    float sq = v.x * v.x + v.y * v.y + v.z * v.z + v.w * v.w;
    for (int o = 16; o > 0; o >>= 1) {
        s  += __shfl_xor_sync(0xffffffff, s, o);
        sq += __shfl_xor_sync(0xffffffff, sq, o);
    }
    __shared__ float ssum[4], ssq[4], stats[2];
    int w = tid >> 5;
    if ((tid & 31) == 0) { ssum[w] = s; ssq[w] = sq; }
    __syncthreads();
    if (tid == 0) {
        float S = ssum[0] + ssum[1] + ssum[2] + ssum[3];
        float Q = ssq[0] + ssq[1] + ssq[2] + ssq[3];
        float mu = S * (1.0f / EMB);
        float var = Q * (1.0f / EMB) - mu * mu;
        stats[0] = mu;
        stats[1] = rsqrtf(var + 1e-5f);
    }
    __syncthreads();
    float mu = stats[0], rs = stats[1];
    int c = tid * 4;
    float4 gg = *reinterpret_cast<const float4*>(g + c);
    float4 bb = *reinterpret_cast<const float4*>(b + c);
    float4 o;
    o.x = (v.x - mu) * rs * gg.x + bb.x;
    o.y = (v.y - mu) * rs * gg.y + bb.y;
    o.z = (v.z - mu) * rs * gg.z + bb.z;
    o.w = (v.w - mu) * rs * gg.w + bb.w;
    *reinterpret_cast<float4*>(Y + (size_t)t * EMB + c) = o;
}

// ---------------- generic SGEMM: C[M,N] = act(A[M,K] @ B[K,N] + bias) + res ----------------
// BM=128, BN=128, BK=8, 256 threads, 8x8 per thread. M must be multiple of 128.
template <int ACT>  // 0 = none, 1 = gelu
__global__ __launch_bounds__(256) void sgemm(const float* __restrict__ A,
                                             const float* __restrict__ B,
                                             const float* __restrict__ bias,
                                             const float* __restrict__ res,
                                             float* __restrict__ C,
                                             int M, int N, int K) {
    __shared__ float As[8][128];
    __shared__ float Bs[8][128];
    int tid = threadIdx.x;
    int row0 = blockIdx.y * 128, col0 = blockIdx.x * 128;
    int aRow = tid >> 1, aCol = (tid & 1) * 4;
    int bRow = tid >> 5, bCol = (tid & 31) * 4;
    int tr = (tid >> 4) * 8, tc = (tid & 15) * 8;

    float acc[8][8];
#pragma unroll
    for (int i = 0; i < 8; i++)
#pragma unroll
        for (int j = 0; j < 8; j++) acc[i][j] = 0.f;

    const float* Ap = A + (size_t)(row0 + aRow) * K + aCol;
    for (int k0 = 0; k0 < K; k0 += 8) {
        float4 av = *reinterpret_cast<const float4*>(Ap + k0);
        As[aCol + 0][aRow] = av.x;
        As[aCol + 1][aRow] = av.y;
        As[aCol + 2][aRow] = av.z;
        As[aCol + 3][aRow] = av.w;
        int gc = col0 + bCol;
        const float* Bp = B + (size_t)(k0 + bRow) * N + gc;
        float4 bv;
        if (gc + 3 < N) {
            bv = *reinterpret_cast<const float4*>(Bp);
        } else {
            bv.x = (gc + 0 < N) ? Bp[0] : 0.f;
            bv.y = (gc + 1 < N) ? Bp[1] : 0.f;
            bv.z = (gc + 2 < N) ? Bp[2] : 0.f;
            bv.w = (gc + 3 < N) ? Bp[3] : 0.f;
        }
        Bs[bRow][bCol + 0] = bv.x;
        Bs[bRow][bCol + 1] = bv.y;
        Bs[bRow][bCol + 2] = bv.z;
        Bs[bRow][bCol + 3] = bv.w;
        __syncthreads();
#pragma unroll
        for (int k = 0; k < 8; k++) {
            float4 ra0 = *reinterpret_cast<const float4*>(&As[k][tr]);
            float4 ra1 = *reinterpret_cast<const float4*>(&As[k][tr + 4]);
            float4 rb0 = *reinterpret_cast<const float4*>(&Bs[k][tc]);
            float4 rb1 = *reinterpret_cast<const float4*>(&Bs[k][tc + 4]);
            float ra[8] = {ra0.x, ra0.y, ra0.z, ra0.w, ra1.x, ra1.y, ra1.z, ra1.w};
            float rb[8] = {rb0.x, rb0.y, rb0.z, rb0.w, rb1.x, rb1.y, rb1.z, rb1.w};
#pragma unroll
            for (int i = 0; i < 8; i++)
#pragma unroll
                for (int j = 0; j < 8; j++) acc[i][j] += ra[i] * rb[j];
        }
        __syncthreads();
    }
#pragma unroll
    for (int i = 0; i < 8; i++) {
        int gr = row0 + tr + i;
#pragma unroll
        for (int j = 0; j < 8; j++) {
            int gc = col0 + tc + j;
            if (gc < N) {
                float v = acc[i][j];
                if (bias) v += bias[gc];
                if (ACT == 1) v = gelu_tanh(v);
                if (res) v += res[(size_t)gr * N + gc];
                C[(size_t)gr * N + gc] = v;
            }
        }
    }
}

// ---------------- flash attention: block = (b,h) x 64-row q tile, K-tile=32 ----------------
// Static shared memory only (~42 KB) -> no cudaFuncSetAttribute needed.
#define KT 32
__global__ __launch_bounds__(128) void attn_kernel() {
    const float* __restrict__ Q = g_q;
    const float* __restrict__ K = g_k;
    const float* __restrict__ V = g_v;
    float* __restrict__ O = g_attn;

    __shared__ float Qs[64 * 64];          // [qrow][d]
    __shared__ float Kts[64 * (KT + 1)];   // [d][krow] transposed, padded
    __shared__ float Vs[KT * 64];          // [krow][d]
    __shared__ float Ss[64 * (KT + 1)];    // [qrow][krow], padded
    __shared__ float rowm[64], rowl[64], rowf[64];

    int bh = blockIdx.x;             // 0..31
    int qt = blockIdx.y;             // 0..15
    int b = bh >> 3, h = bh & 7;
    const size_t base = (size_t)b * SEQ * EMB + h * HD;
    int tid = threadIdx.x;
    int tr = (tid >> 4) * 8;         // q-row group (8 rows)
    int tc = (tid & 15) * 4;         // d-col group (4 cols)
    int sc = (tid & 15) * 2;         // S cols per thread (2)

    // load Q tile (64x64)
    for (int idx = tid; idx < 64 * 16; idx += 128) {
        int r = idx >> 4, c4 = (idx & 15) * 4;
        float4 qv = *reinterpret_cast<const float4*>(Q + base + (size_t)(qt * 64 + r) * EMB + c4);
        Qs[r * 64 + c4 + 0] = qv.x;
        Qs[r * 64 + c4 + 1] = qv.y;
        Qs[r * 64 + c4 + 2] = qv.z;
        Qs[r * 64 + c4 + 3] = qv.w;
    }
    if (tid < 64) { rowm[tid] = -1e30f; rowl[tid] = 0.f; }

    float o[8][4];
#pragma unroll
    for (int i = 0; i < 8; i++)
#pragma unroll
        for (int j = 0; j < 4; j++) o[i][j] = 0.f;
    __syncthreads();

    for (int kt = 0; kt < SEQ / KT; kt++) {
        for (int idx = tid; idx < KT * 16; idx += 128) {
            int r = idx >> 4, c4 = (idx & 15) * 4;
            float4 kv = *reinterpret_cast<const float4*>(K + base + (size_t)(kt * KT + r) * EMB + c4);
            Kts[(c4 + 0) * (KT + 1) + r] = kv.x;
            Kts[(c4 + 1) * (KT + 1) + r] = kv.y;
            Kts[(c4 + 2) * (KT + 1) + r] = kv.z;
            Kts[(c4 + 3) * (KT + 1) + r] = kv.w;
            float4 vv = *reinterpret_cast<const float4*>(V + base + (size_t)(kt * KT + r) * EMB + c4);
            *reinterpret_cast<float4*>(Vs + r * 64 + c4) = vv;
        }
        __syncthreads();
        // S = Q @ K^T * 0.125 ; per thread 8 rows x 2 cols
        float s[8][2];
#pragma unroll
        for (int i = 0; i < 8; i++) { s[i][0] = 0.f; s[i][1] = 0.f; }
        for (int d = 0; d < 64; d++) {
            float rb0 = Kts[d * (KT + 1) + sc];
            float rb1 = Kts[d * (KT + 1) + sc + 1];
#pragma unroll
            for (int i = 0; i < 8; i++) {
                float ra = Qs[(tr + i) * 64 + d];
                s[i][0] += ra * rb0;
                s[i][1] += ra * rb1;
            }
        }
#pragma unroll
        for (int i = 0; i < 8; i++) {
            Ss[(tr + i) * (KT + 1) + sc]     = s[i][0] * 0.125f;
            Ss[(tr + i) * (KT + 1) + sc + 1] = s[i][1] * 0.125f;
        }
        __syncthreads();
        // online softmax per row (one thread per q row)
        if (tid < 64) {
            int r = tid;
            float mo = rowm[r];
            float mx = mo;
#pragma unroll
            for (int j = 0; j < KT; j++) mx = fmaxf(mx, Ss[r * (KT + 1) + j]);
            float f = __expf(mo - mx);
            float l = rowl[r] * f;
#pragma unroll
            for (int j = 0; j < KT; j++) {
                float p = __expf(Ss[r * (KT + 1) + j] - mx);
                Ss[r * (KT + 1) + j] = p;
                l += p;
            }
            rowm[r] = mx;
            rowl[r] = l;
            rowf[r] = f;
        }
        __syncthreads();
        // rescale + O += P @ V
#pragma unroll
        for (int i = 0; i < 8; i++) {
            float f = rowf[tr + i];
#pragma unroll
            for (int j = 0; j < 4; j++) o[i][j] *= f;
        }
        for (int t = 0; t < KT; t++) {
            float4 rv = *reinterpret_cast<const float4*>(Vs + t * 64 + tc);
#pragma unroll
            for (int i = 0; i < 8; i++) {
                float rp = Ss[(tr + i) * (KT + 1) + t];
                o[i][0] += rp * rv.x;
                o[i][1] += rp * rv.y;
                o[i][2] += rp * rv.z;
                o[i][3] += rp * rv.w;
            }
        }
        __syncthreads();
    }
#pragma unroll
    for (int i = 0; i < 8; i++) {
        float inv = 1.0f / rowl[tr + i];
#pragma unroll
        for (int j = 0; j < 4; j++)
            O[base + (size_t)(qt * 64 + tr + i) * EMB + tc + j] = o[i][j] * inv;
    }
}

// ---------------- router: softmax + top-4 + importance/count stats ----------------
__global__ __launch_bounds__(128) void router_topk_kernel() {
    const float* __restrict__ logits = g_logits;
    __shared__ float s_imp[NEXP];
    __shared__ int s_cnt[NEXP];
    int tid = threadIdx.x;
    if (tid < NEXP) { s_imp[tid] = 0.f; s_cnt[tid] = 0; }
    __syncthreads();
    int t = blockIdx.x * 128 + tid;
    float p[NEXP];
    float mx = -1e30f;
#pragma unroll
    for (int e = 0; e < NEXP; e++) {
        p[e] = logits[(size_t)t * NEXP + e];
        mx = fmaxf(mx, p[e]);
    }
    float sum = 0.f;
#pragma unroll
    for (int e = 0; e < NEXP; e++) { p[e] = __expf(p[e] - mx); sum += p[e]; }
    float inv = 1.f / sum;
#pragma unroll
    for (int e = 0; e < NEXP; e++) {
        p[e] *= inv;
        atomicAdd(&s_imp[e], p[e]);
    }
    int idx[TOPK];
    float w[TOPK];
    float tot = 0.f;
#pragma unroll
    for (int k = 0; k < TOPK; k++) {
        float best = -1.f;
        int bi = 0;
#pragma unroll
        for (int e = 0; e < NEXP; e++)
            if (p[e] > best) { best = p[e]; bi = e; }
        idx[k] = bi;
        w[k] = best;
        tot += best;
        p[bi] = -1.f;
        atomicAdd(&s_cnt[bi], 1);
    }
    float it = 1.f / tot;
#pragma unroll
    for (int k = 0; k < TOPK; k++) {
        g_topi[t * TOPK + k] = idx[k];
        g_topw[t * TOPK + k] = w[k] * it;
    }
    __syncthreads();
    if (tid < NEXP) {
        atomicAdd(&g_imp[tid], s_imp[tid]);
        atomicAdd(&g_cnt[tid], s_cnt[tid]);
    }
}

// ---------------- prefix scan over expert counts + aux loss ----------------
__global__ void scan_aux_kernel(float* __restrict__ out, int out_size) {
    if (threadIdx.x == 0) {
        int acc = 0;
        float aux = 0.f;
        for (int e = 0; e < NEXP; e++) {
            g_off[e] = acc;
            acc += g_cnt[e];
            aux += g_imp[e] * (float)g_cnt[e];
        }
        aux *= (float)NEXP / ((float)TOK * (float)TOK);
        if (out_size > TOK * EMB) out[TOK * EMB] = aux;
    }
}

// ---------------- fill per-expert assignment lists ----------------
__global__ __launch_bounds__(128) void fill_assign_kernel() {
    int t = blockIdx.x * 128 + threadIdx.x;
#pragma unroll
    for (int k = 0; k < TOPK; k++) {
        int e = g_topi[t * TOPK + k];
        int pos = atomicAdd(&g_cur[e], 1);
        int gidx = g_off[e] + pos;
        g_atok[gidx] = t;
        g_aw[gidx] = g_topw[t * TOPK + k];
    }
}

__global__ void zero_small_kernel() {
    int i = threadIdx.x;
    if (i < NEXP) { g_imp[i] = 0.f; g_cnt[i] = 0; g_cur[i] = 0; }
}

// ---------------- routed expert GEMM1: H = gelu(gather(h2) @ W1[e] + b1[e]) ----------------
__global__ __launch_bounds__(256) void routed_gemm1(const float* __restrict__ W1all,
                                                    const float* __restrict__ b1all) {
    int e = blockIdx.z;
    int cnt = g_cnt[e];
    int m0 = blockIdx.y * 128;
    if (m0 >= cnt) return;
    int off = g_off[e];
    const float* B = W1all + (size_t)e * EMB * EHID;
    const float* bias = b1all + (size_t)e * EHID;

    __shared__ float As[8][128];
    __shared__ float Bs[8][128];
    int tid = threadIdx.x;
    int col0 = blockIdx.x * 128;
    int aRow = tid >> 1, aCol = (tid & 1) * 4;
    int bRow = tid >> 5, bCol = (tid & 31) * 4;
    int tr = (tid >> 4) * 8, tc = (tid & 15) * 8;

    int m = m0 + aRow;
    int tokrow = (m < cnt) ? g_atok[off + m] : -1;

    float acc[8][8];
#pragma unroll
    for (int i = 0; i < 8; i++)
#pragma unroll
        for (int j = 0; j < 8; j++) acc[i][j] = 0.f;

    for (int k0 = 0; k0 < EMB; k0 += 8) {
        float4 av = make_float4(0.f, 0.f, 0.f, 0.f);
        if (tokrow >= 0)
            av = *reinterpret_cast<const float4*>(g_h2 + (size_t)tokrow * EMB + k0 + aCol);
        As[aCol + 0][aRow] = av.x;
        As[aCol + 1][aRow] = av.y;
        As[aCol + 2][aRow] = av.z;
        As[aCol + 3][aRow] = av.w;
        float4 bv = *reinterpret_cast<const float4*>(B + (size_t)(k0 + bRow) * EHID + col0 + bCol);
        Bs[bRow][bCol + 0] = bv.x;
        Bs[bRow][bCol + 1] = bv.y;
        Bs[bRow][bCol + 2] = bv.z;
        Bs[bRow][bCol + 3] = bv.w;
        __syncthreads();
#pragma unroll
        for (int k = 0; k < 8; k++) {
            float4 ra0 = *reinterpret_cast<const float4*>(&As[k][tr]);
            float4 ra1 = *reinterpret_cast<const float4*>(&As[k][tr + 4]);
            float4 rb0 = *reinterpret_cast<const float4*>(&Bs[k][tc]);
            float4 rb1 = *reinterpret_cast<const float4*>(&Bs[k][tc + 4]);
            float ra[8] = {ra0.x, ra0.y, ra0.z, ra0.w, ra1.x, ra1.y, ra1.z, ra1.w};
            float rb[8] = {rb0.x, rb0.y, rb0.z, rb0.w, rb1.x, rb1.y, rb1.z, rb1.w};
#pragma unroll
            for (int i = 0; i < 8; i++)
#pragma unroll
                for (int j = 0; j < 8; j++) acc[i][j] += ra[i] * rb[j];
        }
        __syncthreads();
    }
#pragma unroll
    for (int i = 0; i < 8; i++) {
        int mi = m0 + tr + i;
        if (mi < cnt) {
#pragma unroll
            for (int j = 0; j < 8; j++) {
                int gc = col0 + tc + j;
                g_H[(size_t)(off + mi) * EHID + gc] = gelu_tanh(acc[i][j] + bias[gc]);
            }
        }
    }
}

// ---------------- routed expert GEMM2: out += gate * (H @ W2[e] + b2[e]) ----------------
__global__ __launch_bounds__(256) void routed_gemm2(const float* __restrict__ W2all,
                                                    const float* __restrict__ b2all,
                                                    float* __restrict__ out) {
    int e = blockIdx.z;
    int cnt = g_cnt[e];
    int m0 = blockIdx.y * 128;
    if (m0 >= cnt) return;
    int off = g_off[e];
    const float* B = W2all + (size_t)e * EHID * EMB;
    const float* bias = b2all + (size_t)e * EMB;

    __shared__ float As[8][128];
    __shared__ float Bs[8][128];
    int tid = threadIdx.x;
    int col0 = blockIdx.x * 128;
    int aRow = tid >> 1, aCol = (tid & 1) * 4;
    int bRow = tid >> 5, bCol = (tid & 31) * 4;
    int tr = (tid >> 4) * 8, tc = (tid & 15) * 8;

    int m = m0 + aRow;
    bool avalid = (m < cnt);

    float acc[8][8];
#pragma unroll
    for (int i = 0; i < 8; i++)
#pragma unroll
        for (int j = 0; j < 8; j++) acc[i][j] = 0.f;

    for (int k0 = 0; k0 < EHID; k0 += 8) {
        float4 av = make_float4(0.f, 0.f, 0.f, 0.f);
        if (avalid)
            av = *reinterpret_cast<const float4*>(g_H + (size_t)(off + m) * EHID + k0 + aCol);
        As[aCol + 0][aRow] = av.x;
        As[aCol + 1][aRow] = av.y;
        As[aCol + 2][aRow] = av.z;
        As[aCol + 3][aRow] = av.w;
        float4 bv = *reinterpret_cast<const float4*>(B + (size_t)(k0 + bRow) * EMB + col0 + bCol);
        Bs[bRow][bCol + 0] = bv.x;
        Bs[bRow][bCol + 1] = bv.y;
        Bs[bRow][bCol + 2] = bv.z;
        Bs[bRow][bCol + 3] = bv.w;
        __syncthreads();
#pragma unroll
        for (int k = 0; k < 8; k++) {
            float4 ra0 = *reinterpret_cast<const float4*>(&As[k][tr]);
            float4 ra1 = *reinterpret_cast<const float4*>(&As[k][tr + 4]);
            float4 rb0 = *reinterpret_cast<const float4*>(&Bs[k][tc]);
            float4 rb1 = *reinterpret_cast<const float4*>(&Bs[k][tc + 4]);
            float ra[8] = {ra0.x, ra0.y, ra0.z, ra0.w, ra1.x, ra1.y, ra1.z, ra1.w};
            float rb[8] = {rb0.x, rb0.y, rb0.z, rb0.w, rb1.x, rb1.y, rb1.z, rb1.w};
#pragma unroll
            for (int i = 0; i < 8; i++)
#pragma unroll
                for (int j = 0; j < 8; j++) acc[i][j] += ra[i] * rb[j];
        }
        __syncthreads();
    }
#pragma unroll
    for (int i = 0; i < 8; i++) {
        int mi = m0 + tr + i;
        if (mi < cnt) {
            int tok = g_atok[off + mi];
            float wgt = g_aw[off + mi];
#pragma unroll
            for (int j = 0; j < 8; j++) {
                int gc = col0 + tc + j;
                atomicAdd(&out[(size_t)tok * EMB + gc], (acc[i][j] + bias[gc]) * wgt);
            }
        }
    }
}

// ---------------- launch ----------------
extern "C" void kernel_launch(void* const* d_in, const int* in_sizes, int n_in,
                              void* d_out, int out_size) {
    const float* x        = (const float*)d_in[0];
    const float* ln1_g    = (const float*)d_in[1];
    const float* ln1_b    = (const float*)d_in[2];
    const float* wq       = (const float*)d_in[3];
    const float* bq       = (const float*)d_in[4];
    const float* wk       = (const float*)d_in[5];
    const float* bk       = (const float*)d_in[6];
    const float* wv       = (const float*)d_in[7];
    const float* bv       = (const float*)d_in[8];
    const float* wo       = (const float*)d_in[9];
    const float* bo       = (const float*)d_in[10];
    const float* ln2_g    = (const float*)d_in[11];
    const float* ln2_b    = (const float*)d_in[12];
    const float* router_a = (const float*)d_in[13];
    const float* router_b = (const float*)d_in[14];
    const float* re_w1    = (const float*)d_in[15];
    const float* re_b1    = (const float*)d_in[16];
    const float* re_w2    = (const float*)d_in[17];
    const float* re_b2    = (const float*)d_in[18];
    const float* se_w1    = (const float*)d_in[19];
    const float* se_b1    = (const float*)d_in[20];
    const float* se_w2    = (const float*)d_in[21];
    const float* se_b2    = (const float*)d_in[22];
    float* out = (float*)d_out;

    // Host-visible addresses of device scratch (non-stream API, capture-safe,
    // no graph nodes; re-done every call so behavior is call-count independent).
    float *p_h1, *p_q, *p_k, *p_v, *p_attn, *p_x1, *p_h2, *p_rlat, *p_logits, *p_hs;
    cudaGetSymbolAddress((void**)&p_h1, g_h1);
    cudaGetSymbolAddress((void**)&p_q, g_q);
    cudaGetSymbolAddress((void**)&p_k, g_k);
    cudaGetSymbolAddress((void**)&p_v, g_v);
    cudaGetSymbolAddress((void**)&p_attn, g_attn);
    cudaGetSymbolAddress((void**)&p_x1, g_x1);
    cudaGetSymbolAddress((void**)&p_h2, g_h2);
    cudaGetSymbolAddress((void**)&p_rlat, g_rlat);
    cudaGetSymbolAddress((void**)&p_logits, g_logits);
    cudaGetSymbolAddress((void**)&p_hs, g_hs);

    zero_small_kernel<<<1, 32>>>();
    ln_kernel<<<TOK, 128>>>(x, ln1_g, ln1_b, p_h1);

    dim3 g512(4, 32);  // N=512 tiles x M=4096 tiles
    sgemm<0><<<g512, 256>>>(p_h1, wq, bq, nullptr, p_q, TOK, EMB, EMB);
    sgemm<0><<<g512, 256>>>(p_h1, wk, bk, nullptr, p_k, TOK, EMB, EMB);
    sgemm<0><<<g512, 256>>>(p_h1, wv, bv, nullptr, p_v, TOK, EMB, EMB);

    attn_kernel<<<dim3(32, 16), 128>>>();

    sgemm<0><<<g512, 256>>>(p_attn, wo, bo, x, p_x1, TOK, EMB, EMB);  // + residual x
    ln_kernel<<<TOK, 128>>>(p_x1, ln2_g, ln2_b, p_h2);

    // router (low-rank)
    sgemm<0><<<dim3(1, 32), 256>>>(p_h2, router_a, nullptr, nullptr, p_rlat, TOK, RRANK, EMB);
    sgemm<0><<<dim3(1, 32), 256>>>(p_rlat, router_b, nullptr, nullptr, p_logits, TOK, NEXP, RRANK);
    router_topk_kernel<<<TOK / 128, 128>>>();
    scan_aux_kernel<<<1, 32>>>(out, out_size);
    fill_assign_kernel<<<TOK / 128, 128>>>();

    // routed experts (sparse, grouped)
    routed_gemm1<<<dim3(4, 128, 32), 256>>>(re_w1, re_b1);

    // shared expert
    sgemm<1><<<dim3(32, 32), 256>>>(p_h2, se_w1, se_b1, nullptr, p_hs, TOK, SHID, EMB);
    sgemm<0><<<dim3(4, 32), 256>>>(p_hs, se_w2, se_b2, p_x1, out, TOK, EMB, SHID);  // writes x1+shared

    // routed contribution accumulates on top
    routed_gemm2<<<dim3(4, 128, 32), 256>>>(re_w2, re_b2, out);
}

// round 6
// speedup vs baseline: 1.2775x; 1.2775x over previous
#include <cuda_runtime.h>
#include <math.h>

// ---------------- problem constants ----------------
#define TOK   4096          // B*S = 4*1024
#define SEQ   1024
#define BATCH 4
#define EMB   512
#define NH    8
#define HD    64
#define NEXP  32
#define TOPK  4
#define RRANK 64
#define SHID  4096
#define EHID  512

// ---------------- device scratch (static, allocation-free) ----------------
__device__ float g_h1[TOK * EMB];
__device__ float g_q[TOK * EMB];
__device__ float g_k[TOK * EMB];
__device__ float g_v[TOK * EMB];
__device__ float g_attn[TOK * EMB];
__device__ float g_x1[TOK * EMB];
__device__ float g_h2[TOK * EMB];
__device__ float g_rlat[TOK * RRANK];
__device__ float g_logits[TOK * NEXP];
__device__ int   g_topi[TOK * TOPK];
__device__ float g_topw[TOK * TOPK];
__device__ float g_imp[NEXP];
__device__ int   g_cnt[NEXP];
__device__ int   g_off[NEXP];
__device__ int   g_cur[NEXP];
__device__ int   g_atok[TOK * TOPK];
__device__ float g_aw[TOK * TOPK];
__device__ float g_H[TOK * TOPK * EHID];   // routed hidden
__device__ float g_hs[TOK * SHID];         // shared-expert hidden

// ---------------- helpers ----------------
__device__ __forceinline__ float gelu_tanh(float x) {
    float x3 = x * x * x;
    return 0.5f * x * (1.0f + tanhf(0.7978845608028654f * (x + 0.044715f * x3)));
}

__device__ __forceinline__ unsigned f2tf32(float f) {
    unsigned r;
    asm("cvt.rna.tf32.f32 %0, %1;" : "=r"(r) : "f"(f));
    return r;
}

// split f into hi (tf32) + lo (tf32 of remainder)
__device__ __forceinline__ void tf32_split(float f, unsigned& hi, unsigned& lo) {
    hi = f2tf32(f);
    lo = f2tf32(f - __uint_as_float(hi));
}

__device__ __forceinline__ void mma_tf32(float& c0, float& c1, float& c2, float& c3,
                                         unsigned a0, unsigned a1, unsigned a2, unsigned a3,
                                         unsigned b0, unsigned b1) {
    asm volatile(
        "mma.sync.aligned.m16n8k8.row.col.f32.tf32.tf32.f32 "
        "{%0,%1,%2,%3}, {%4,%5,%6,%7}, {%8,%9}, {%0,%1,%2,%3};"
        : "+f"(c0), "+f"(c1), "+f"(c2), "+f"(c3)
        : "r"(a0), "r"(a1), "r"(a2), "r"(a3), "r"(b0), "r"(b1));
}

// ================= 3xTF32 tensor-core GEMM (fp32-accurate) =================
// C[M,N] = act(A[M,K] @ B[K,N] + bias) (+ res)
// BM=128, BN=128, BK=32. 256 threads = 8 warps (2 M x 4 N), warp tile 64x32.
// fp32 tiles in smem; hi/lo tf32 split at fragment load; 3 MMAs per tile:
// hi*hi + lo*hi + hi*lo  (lo*lo term ~2^-22, dropped).
#define APAD 36
#define BPAD 136

// one k-slab of 3xtf32 mma work, shared by all gemm kernels
#define TGEMM_MAINLOOP(AsArr, BsArr)                                            \
    for (int kk = 0; kk < 4; kk++) {                                            \
        int kb = kk * 8;                                                        \
        unsigned ah[4][4], al[4][4], bh[4][2], bl[4][2];                        \
        _Pragma("unroll")                                                       \
        for (int mt = 0; mt < 4; mt++) {                                        \
            int mb = wm * 64 + mt * 16;                                         \
            tf32_split(AsArr[(mb + g) * APAD + kb + t],       ah[mt][0], al[mt][0]); \
            tf32_split(AsArr[(mb + g + 8) * APAD + kb + t],   ah[mt][1], al[mt][1]); \
            tf32_split(AsArr[(mb + g) * APAD + kb + t + 4],   ah[mt][2], al[mt][2]); \
            tf32_split(AsArr[(mb + g + 8) * APAD + kb + t + 4], ah[mt][3], al[mt][3]); \
        }                                                                       \
        _Pragma("unroll")                                                       \
        for (int nt = 0; nt < 4; nt++) {                                        \
            int nb = wn * 32 + nt * 8;                                          \
            tf32_split(BsArr[(kb + t) * BPAD + nb + g],     bh[nt][0], bl[nt][0]); \
            tf32_split(BsArr[(kb + t + 4) * BPAD + nb + g], bh[nt][1], bl[nt][1]); \
        }                                                                       \
        _Pragma("unroll")                                                       \
        for (int mt = 0; mt < 4; mt++)                                          \
            _Pragma("unroll")                                                   \
            for (int nt = 0; nt < 4; nt++) {                                    \
                mma_tf32(c[mt][nt][0], c[mt][nt][1], c[mt][nt][2], c[mt][nt][3],\
                         al[mt][0], al[mt][1], al[mt][2], al[mt][3],            \
                         bh[nt][0], bh[nt][1]);                                 \
                mma_tf32(c[mt][nt][0], c[mt][nt][1], c[mt][nt][2], c[mt][nt][3],\
                         ah[mt][0], ah[mt][1], ah[mt][2], ah[mt][3],            \
                         bl[nt][0], bl[nt][1]);                                 \
                mma_tf32(c[mt][nt][0], c[mt][nt][1], c[mt][nt][2], c[mt][nt][3],\
                         ah[mt][0], ah[mt][1], ah[mt][2], ah[mt][3],            \
                         bh[nt][0], bh[nt][1]);                                 \
            }                                                                   \
    }

template <int ACT>  // 0 = none, 1 = gelu
__global__ __launch_bounds__(256) void tgemm(const float* __restrict__ A,
                                             const float* __restrict__ B,
                                             const float* __restrict__ bias,
                                             const float* __restrict__ res,
                                             float* __restrict__ C,
                                             int M, int N, int K) {
    __shared__ float As[128 * APAD];
    __shared__ float Bs[32 * BPAD];

    int tid = threadIdx.x;
    int warp = tid >> 5, lane = tid & 31;
    int wm = warp >> 2, wn = warp & 3;            // warp grid 2 x 4
    int g = lane >> 2, t = lane & 3;              // mma lane mapping
    int row0 = blockIdx.y * 128, col0 = blockIdx.x * 128;

    int arow = tid >> 1, acb = (tid & 1) * 16;
    int brow = tid >> 3, bcb = (tid & 7) * 16;

    float c[4][4][4];
#pragma unroll
    for (int i = 0; i < 4; i++)
#pragma unroll
        for (int j = 0; j < 4; j++) { c[i][j][0] = c[i][j][1] = c[i][j][2] = c[i][j][3] = 0.f; }

    const float* Ap = A + (size_t)(row0 + arow) * K + acb;
    for (int k0 = 0; k0 < K; k0 += 32) {
#pragma unroll
        for (int i = 0; i < 4; i++)
            *reinterpret_cast<float4*>(&As[arow * APAD + acb + i * 4]) =
                *reinterpret_cast<const float4*>(Ap + k0 + i * 4);
        const float* Bp = B + (size_t)(k0 + brow) * N + col0 + bcb;
#pragma unroll
        for (int i = 0; i < 4; i++)
            *reinterpret_cast<float4*>(&Bs[brow * BPAD + bcb + i * 4]) =
                *reinterpret_cast<const float4*>(Bp + i * 4);
        __syncthreads();
        TGEMM_MAINLOOP(As, Bs)
        __syncthreads();
    }
    // epilogue: c0:(m=mb+g, n=nb+2t) c1:(.., +1) c2:(mb+g+8, 2t) c3:(.., +1)
#pragma unroll
    for (int mt = 0; mt < 4; mt++) {
        int mb = row0 + wm * 64 + mt * 16;
#pragma unroll
        for (int nt = 0; nt < 4; nt++) {
            int nb = col0 + wn * 32 + nt * 8 + 2 * t;
#pragma unroll
            for (int half = 0; half < 2; half++) {
                int r = mb + g + half * 8;
                float v0 = c[mt][nt][half * 2 + 0];
                float v1 = c[mt][nt][half * 2 + 1];
                if (bias) { v0 += bias[nb]; v1 += bias[nb + 1]; }
                if (ACT == 1) { v0 = gelu_tanh(v0); v1 = gelu_tanh(v1); }
                if (res) {
                    v0 += res[(size_t)r * N + nb];
                    v1 += res[(size_t)r * N + nb + 1];
                }
                C[(size_t)r * N + nb] = v0;
                C[(size_t)r * N + nb + 1] = v1;
            }
        }
    }
}

// ---------------- routed expert GEMM1: H = gelu(gather(h2) @ W1[e] + b1[e]) ----
__global__ __launch_bounds__(256) void routed_tgemm1(const float* __restrict__ W1all,
                                                     const float* __restrict__ b1all) {
    int e = blockIdx.z;
    int cnt = g_cnt[e];
    int m0 = blockIdx.y * 128;
    if (m0 >= cnt) return;
    int off = g_off[e];
    const float* B = W1all + (size_t)e * EMB * EHID;
    const float* bias = b1all + (size_t)e * EHID;

    __shared__ float As[128 * APAD];
    __shared__ float Bs[32 * BPAD];

    int tid = threadIdx.x;
    int warp = tid >> 5, lane = tid & 31;
    int wm = warp >> 2, wn = warp & 3;
    int g = lane >> 2, t = lane & 3;
    int col0 = blockIdx.x * 128;

    int arow = tid >> 1, acb = (tid & 1) * 16;
    int brow = tid >> 3, bcb = (tid & 7) * 16;
    int m = m0 + arow;
    int tokrow = (m < cnt) ? g_atok[off + m] : -1;

    float c[4][4][4];
#pragma unroll
    for (int i = 0; i < 4; i++)
#pragma unroll
        for (int j = 0; j < 4; j++) { c[i][j][0] = c[i][j][1] = c[i][j][2] = c[i][j][3] = 0.f; }

    for (int k0 = 0; k0 < EMB; k0 += 32) {
#pragma unroll
        for (int i = 0; i < 4; i++) {
            float4 v = make_float4(0.f, 0.f, 0.f, 0.f);
            if (tokrow >= 0)
                v = *reinterpret_cast<const float4*>(g_h2 + (size_t)tokrow * EMB + k0 + acb + i * 4);
            *reinterpret_cast<float4*>(&As[arow * APAD + acb + i * 4]) = v;
        }
        const float* Bp = B + (size_t)(k0 + brow) * EHID + col0 + bcb;
#pragma unroll
        for (int i = 0; i < 4; i++)
            *reinterpret_cast<float4*>(&Bs[brow * BPAD + bcb + i * 4]) =
                *reinterpret_cast<const float4*>(Bp + i * 4);
        __syncthreads();
        TGEMM_MAINLOOP(As, Bs)
        __syncthreads();
    }
#pragma unroll
    for (int mt = 0; mt < 4; mt++) {
        int mb = m0 + wm * 64 + mt * 16;
#pragma unroll
        for (int nt = 0; nt < 4; nt++) {
            int nb = col0 + wn * 32 + nt * 8 + 2 * t;
#pragma unroll
            for (int half = 0; half < 2; half++) {
                int mi = mb + g + half * 8;
                if (mi < cnt) {
                    float v0 = gelu_tanh(c[mt][nt][half * 2 + 0] + bias[nb]);
                    float v1 = gelu_tanh(c[mt][nt][half * 2 + 1] + bias[nb + 1]);
                    g_H[(size_t)(off + mi) * EHID + nb] = v0;
                    g_H[(size_t)(off + mi) * EHID + nb + 1] = v1;
                }
            }
        }
    }
}

// ---------------- routed expert GEMM2: out += gate * (H @ W2[e] + b2[e]) -------
__global__ __launch_bounds__(256) void routed_tgemm2(const float* __restrict__ W2all,
                                                     const float* __restrict__ b2all,
                                                     float* __restrict__ out) {
    int e = blockIdx.z;
    int cnt = g_cnt[e];
    int m0 = blockIdx.y * 128;
    if (m0 >= cnt) return;
    int off = g_off[e];
    const float* B = W2all + (size_t)e * EHID * EMB;
    const float* bias = b2all + (size_t)e * EMB;

    __shared__ float As[128 * APAD];
    __shared__ float Bs[32 * BPAD];

    int tid = threadIdx.x;
    int warp = tid >> 5, lane = tid & 31;
    int wm = warp >> 2, wn = warp & 3;
    int g = lane >> 2, t = lane & 3;
    int col0 = blockIdx.x * 128;

    int arow = tid >> 1, acb = (tid & 1) * 16;
    int brow = tid >> 3, bcb = (tid & 7) * 16;
    int m = m0 + arow;
    bool avalid = (m < cnt);

    float c[4][4][4];
#pragma unroll
    for (int i = 0; i < 4; i++)
#pragma unroll
        for (int j = 0; j < 4; j++) { c[i][j][0] = c[i][j][1] = c[i][j][2] = c[i][j][3] = 0.f; }

    for (int k0 = 0; k0 < EHID; k0 += 32) {
#pragma unroll
        for (int i = 0; i < 4; i++) {
            float4 v = make_float4(0.f, 0.f, 0.f, 0.f);
            if (avalid)
                v = *reinterpret_cast<const float4*>(g_H + (size_t)(off + m) * EHID + k0 + acb + i * 4);
            *reinterpret_cast<float4*>(&As[arow * APAD + acb + i * 4]) = v;
        }
        const float* Bp = B + (size_t)(k0 + brow) * EMB + col0 + bcb;
#pragma unroll
        for (int i = 0; i < 4; i++)
            *reinterpret_cast<float4*>(&Bs[brow * BPAD + bcb + i * 4]) =
                *reinterpret_cast<const float4*>(Bp + i * 4);
        __syncthreads();
        TGEMM_MAINLOOP(As, Bs)
        __syncthreads();
    }
#pragma unroll
    for (int mt = 0; mt < 4; mt++) {
        int mb = m0 + wm * 64 + mt * 16;
#pragma unroll
        for (int nt = 0; nt < 4; nt++) {
            int nb = col0 + wn * 32 + nt * 8 + 2 * t;
#pragma unroll
            for (int half = 0; half < 2; half++) {
                int mi = mb + g + half * 8;
                if (mi < cnt) {
                    int tok = g_atok[off + mi];
                    float wgt = g_aw[off + mi];
                    atomicAdd(&out[(size_t)tok * EMB + nb],
                              (c[mt][nt][half * 2 + 0] + bias[nb]) * wgt);
                    atomicAdd(&out[(size_t)tok * EMB + nb + 1],
                              (c[mt][nt][half * 2 + 1] + bias[nb + 1]) * wgt);
                }
            }
        }
    }
}

// ---------------- LayerNorm ----------------
__global__ __launch_bounds__(128) void ln_kernel(const float* __restrict__ X,
                                                 const float* __restrict__ g,
                                                 const float* __restrict__ b,
                                                 float* __restrict__ Y) {
    int t = blockIdx.x;
    int tid = threadIdx.x;
    const float4 v = *reinterpret_cast<const float4*>(X + (size_t)t * EMB + tid * 4);
    float s  = v.x + v.y + v.z + v.w;
    float sq = v.x * v.x + v.y * v.y + v.z * v.z + v.w * v.w;
    for (int o = 16; o > 0; o >>= 1) {
        s  += __shfl_xor_sync(0xffffffff, s, o);
        sq += __shfl_xor_sync(0xffffffff, sq, o);
    }
    __shared__ float ssum[4], ssq[4], stats[2];
    int w = tid >> 5;
    if ((tid & 31) == 0) { ssum[w] = s; ssq[w] = sq; }
    __syncthreads();
    if (tid == 0) {
        float S = ssum[0] + ssum[1] + ssum[2] + ssum[3];
        float Q = ssq[0] + ssq[1] + ssq[2] + ssq[3];
        float mu = S * (1.0f / EMB);
        float var = Q * (1.0f / EMB) - mu * mu;
        stats[0] = mu;
        stats[1] = rsqrtf(var + 1e-5f);
    }
    __syncthreads();
    float mu = stats[0], rs = stats[1];
    int cc = tid * 4;
    float4 gg = *reinterpret_cast<const float4*>(g + cc);
    float4 bb = *reinterpret_cast<const float4*>(b + cc);
    float4 o;
    o.x = (v.x - mu) * rs * gg.x + bb.x;
    o.y = (v.y - mu) * rs * gg.y + bb.y;
    o.z = (v.z - mu) * rs * gg.z + bb.z;
    o.w = (v.w - mu) * rs * gg.w + bb.w;
    *reinterpret_cast<float4*>(Y + (size_t)t * EMB + cc) = o;
}

// ---------------- fp32 SGEMM (router only, small N) ----------------
template <int ACT>
__global__ __launch_bounds__(256) void sgemm(const float* __restrict__ A,
                                             const float* __restrict__ B,
                                             const float* __restrict__ bias,
                                             const float* __restrict__ res,
                                             float* __restrict__ C,
                                             int M, int N, int K) {
    __shared__ float As[8][128];
    __shared__ float Bs[8][128];
    int tid = threadIdx.x;
    int row0 = blockIdx.y * 128, col0 = blockIdx.x * 128;
    int aRow = tid >> 1, aCol = (tid & 1) * 4;
    int bRow = tid >> 5, bCol = (tid & 31) * 4;
    int tr = (tid >> 4) * 8, tc = (tid & 15) * 8;

    float acc[8][8];
#pragma unroll
    for (int i = 0; i < 8; i++)
#pragma unroll
        for (int j = 0; j < 8; j++) acc[i][j] = 0.f;

    const float* Ap = A + (size_t)(row0 + aRow) * K + aCol;
    for (int k0 = 0; k0 < K; k0 += 8) {
        float4 av = *reinterpret_cast<const float4*>(Ap + k0);
        As[aCol + 0][aRow] = av.x;
        As[aCol + 1][aRow] = av.y;
        As[aCol + 2][aRow] = av.z;
        As[aCol + 3][aRow] = av.w;
        int gc = col0 + bCol;
        const float* Bp = B + (size_t)(k0 + bRow) * N + gc;
        float4 bv;
        if (gc + 3 < N) {
            bv = *reinterpret_cast<const float4*>(Bp);
        } else {
            bv.x = (gc + 0 < N) ? Bp[0] : 0.f;
            bv.y = (gc + 1 < N) ? Bp[1] : 0.f;
            bv.z = (gc + 2 < N) ? Bp[2] : 0.f;
            bv.w = (gc + 3 < N) ? Bp[3] : 0.f;
        }
        Bs[bRow][bCol + 0] = bv.x;
        Bs[bRow][bCol + 1] = bv.y;
        Bs[bRow][bCol + 2] = bv.z;
        Bs[bRow][bCol + 3] = bv.w;
        __syncthreads();
#pragma unroll
        for (int k = 0; k < 8; k++) {
            float4 ra0 = *reinterpret_cast<const float4*>(&As[k][tr]);
            float4 ra1 = *reinterpret_cast<const float4*>(&As[k][tr + 4]);
            float4 rb0 = *reinterpret_cast<const float4*>(&Bs[k][tc]);
            float4 rb1 = *reinterpret_cast<const float4*>(&Bs[k][tc + 4]);
            float ra[8] = {ra0.x, ra0.y, ra0.z, ra0.w, ra1.x, ra1.y, ra1.z, ra1.w};
            float rb[8] = {rb0.x, rb0.y, rb0.z, rb0.w, rb1.x, rb1.y, rb1.z, rb1.w};
#pragma unroll
            for (int i = 0; i < 8; i++)
#pragma unroll
                for (int j = 0; j < 8; j++) acc[i][j] += ra[i] * rb[j];
        }
        __syncthreads();
    }
#pragma unroll
    for (int i = 0; i < 8; i++) {
        int gr = row0 + tr + i;
#pragma unroll
        for (int j = 0; j < 8; j++) {
            int gc = col0 + tc + j;
            if (gc < N) {
                float v = acc[i][j];
                if (bias) v += bias[gc];
                if (ACT == 1) v = gelu_tanh(v);
                if (res) v += res[(size_t)gr * N + gc];
                C[(size_t)gr * N + gc] = v;
            }
        }
    }
}

// ---------------- flash attention (fp32, static smem) ----------------
#define KT 32
__global__ __launch_bounds__(128) void attn_kernel() {
    const float* __restrict__ Q = g_q;
    const float* __restrict__ K = g_k;
    const float* __restrict__ V = g_v;
    float* __restrict__ O = g_attn;

    __shared__ float Qs[64 * 64];
    __shared__ float Kts[64 * (KT + 1)];
    __shared__ float Vs[KT * 64];
    __shared__ float Ss[64 * (KT + 1)];
    __shared__ float rowm[64], rowl[64], rowf[64];

    int bh = blockIdx.x;
    int qt = blockIdx.y;
    int b = bh >> 3, h = bh & 7;
    const size_t base = (size_t)b * SEQ * EMB + h * HD;
    int tid = threadIdx.x;
    int tr = (tid >> 4) * 8;
    int tc = (tid & 15) * 4;
    int sc = (tid & 15) * 2;

    for (int idx = tid; idx < 64 * 16; idx += 128) {
        int r = idx >> 4, c4 = (idx & 15) * 4;
        float4 qv = *reinterpret_cast<const float4*>(Q + base + (size_t)(qt * 64 + r) * EMB + c4);
        Qs[r * 64 + c4 + 0] = qv.x;
        Qs[r * 64 + c4 + 1] = qv.y;
        Qs[r * 64 + c4 + 2] = qv.z;
        Qs[r * 64 + c4 + 3] = qv.w;
    }
    if (tid < 64) { rowm[tid] = -1e30f; rowl[tid] = 0.f; }

    float o[8][4];
#pragma unroll
    for (int i = 0; i < 8; i++)
#pragma unroll
        for (int j = 0; j < 4; j++) o[i][j] = 0.f;
    __syncthreads();

    for (int kt = 0; kt < SEQ / KT; kt++) {
        for (int idx = tid; idx < KT * 16; idx += 128) {
            int r = idx >> 4, c4 = (idx & 15) * 4;
            float4 kv = *reinterpret_cast<const float4*>(K + base + (size_t)(kt * KT + r) * EMB + c4);
            Kts[(c4 + 0) * (KT + 1) + r] = kv.x;
            Kts[(c4 + 1) * (KT + 1) + r] = kv.y;
            Kts[(c4 + 2) * (KT + 1) + r] = kv.z;
            Kts[(c4 + 3) * (KT + 1) + r] = kv.w;
            float4 vv = *reinterpret_cast<const float4*>(V + base + (size_t)(kt * KT + r) * EMB + c4);
            *reinterpret_cast<float4*>(Vs + r * 64 + c4) = vv;
        }
        __syncthreads();
        float s[8][2];
#pragma unroll
        for (int i = 0; i < 8; i++) { s[i][0] = 0.f; s[i][1] = 0.f; }
        for (int d = 0; d < 64; d++) {
            float rb0 = Kts[d * (KT + 1) + sc];
            float rb1 = Kts[d * (KT + 1) + sc + 1];
#pragma unroll
            for (int i = 0; i < 8; i++) {
                float ra = Qs[(tr + i) * 64 + d];
                s[i][0] += ra * rb0;
                s[i][1] += ra * rb1;
            }
        }
#pragma unroll
        for (int i = 0; i < 8; i++) {
            Ss[(tr + i) * (KT + 1) + sc]     = s[i][0] * 0.125f;
            Ss[(tr + i) * (KT + 1) + sc + 1] = s[i][1] * 0.125f;
        }
        __syncthreads();
        if (tid < 64) {
            int r = tid;
            float mo = rowm[r];
            float mx = mo;
#pragma unroll
            for (int j = 0; j < KT; j++) mx = fmaxf(mx, Ss[r * (KT + 1) + j]);
            float f = __expf(mo - mx);
            float l = rowl[r] * f;
#pragma unroll
            for (int j = 0; j < KT; j++) {
                float p = __expf(Ss[r * (KT + 1) + j] - mx);
                Ss[r * (KT + 1) + j] = p;
                l += p;
            }
            rowm[r] = mx;
            rowl[r] = l;
            rowf[r] = f;
        }
        __syncthreads();
#pragma unroll
        for (int i = 0; i < 8; i++) {
            float f = rowf[tr + i];
#pragma unroll
            for (int j = 0; j < 4; j++) o[i][j] *= f;
        }
        for (int t = 0; t < KT; t++) {
            float4 rv = *reinterpret_cast<const float4*>(Vs + t * 64 + tc);
#pragma unroll
            for (int i = 0; i < 8; i++) {
                float rp = Ss[(tr + i) * (KT + 1) + t];
                o[i][0] += rp * rv.x;
                o[i][1] += rp * rv.y;
                o[i][2] += rp * rv.z;
                o[i][3] += rp * rv.w;
            }
        }
        __syncthreads();
    }
#pragma unroll
    for (int i = 0; i < 8; i++) {
        float inv = 1.0f / rowl[tr + i];
#pragma unroll
        for (int j = 0; j < 4; j++)
            O[base + (size_t)(qt * 64 + tr + i) * EMB + tc + j] = o[i][j] * inv;
    }
}

// ---------------- router: softmax + top-4 + stats ----------------
__global__ __launch_bounds__(128) void router_topk_kernel() {
    const float* __restrict__ logits = g_logits;
    __shared__ float s_imp[NEXP];
    __shared__ int s_cnt[NEXP];
    int tid = threadIdx.x;
    if (tid < NEXP) { s_imp[tid] = 0.f; s_cnt[tid] = 0; }
    __syncthreads();
    int t = blockIdx.x * 128 + tid;
    float p[NEXP];
    float mx = -1e30f;
#pragma unroll
    for (int e = 0; e < NEXP; e++) {
        p[e] = logits[(size_t)t * NEXP + e];
        mx = fmaxf(mx, p[e]);
    }
    float sum = 0.f;
#pragma unroll
    for (int e = 0; e < NEXP; e++) { p[e] = __expf(p[e] - mx); sum += p[e]; }
    float inv = 1.f / sum;
#pragma unroll
    for (int e = 0; e < NEXP; e++) {
        p[e] *= inv;
        atomicAdd(&s_imp[e], p[e]);
    }
    int idx[TOPK];
    float w[TOPK];
    float tot = 0.f;
#pragma unroll
    for (int k = 0; k < TOPK; k++) {
        float best = -1.f;
        int bi = 0;
#pragma unroll
        for (int e = 0; e < NEXP; e++)
            if (p[e] > best) { best = p[e]; bi = e; }
        idx[k] = bi;
        w[k] = best;
        tot += best;
        p[bi] = -1.f;
        atomicAdd(&s_cnt[bi], 1);
    }
    float it = 1.f / tot;
#pragma unroll
    for (int k = 0; k < TOPK; k++) {
        g_topi[t * TOPK + k] = idx[k];
        g_topw[t * TOPK + k] = w[k] * it;
    }
    __syncthreads();
    if (tid < NEXP) {
        atomicAdd(&g_imp[tid], s_imp[tid]);
        atomicAdd(&g_cnt[tid], s_cnt[tid]);
    }
}

// ---------------- prefix scan + aux loss ----------------
__global__ void scan_aux_kernel(float* __restrict__ out, int out_size) {
    if (threadIdx.x == 0) {
        int acc = 0;
        float aux = 0.f;
        for (int e = 0; e < NEXP; e++) {
            g_off[e] = acc;
            acc += g_cnt[e];
            aux += g_imp[e] * (float)g_cnt[e];
        }
        aux *= (float)NEXP / ((float)TOK * (float)TOK);
        if (out_size > TOK * EMB) out[TOK * EMB] = aux;
    }
}

// ---------------- fill per-expert assignment lists ----------------
__global__ __launch_bounds__(128) void fill_assign_kernel() {
    int t = blockIdx.x * 128 + threadIdx.x;
#pragma unroll
    for (int k = 0; k < TOPK; k++) {
        int e = g_topi[t * TOPK + k];
        int pos = atomicAdd(&g_cur[e], 1);
        int gidx = g_off[e] + pos;
        g_atok[gidx] = t;
        g_aw[gidx] = g_topw[t * TOPK + k];
    }
}

__global__ void zero_small_kernel() {
    int i = threadIdx.x;
    if (i < NEXP) { g_imp[i] = 0.f; g_cnt[i] = 0; g_cur[i] = 0; }
}

// ---------------- launch ----------------
extern "C" void kernel_launch(void* const* d_in, const int* in_sizes, int n_in,
                              void* d_out, int out_size) {
    const float* x        = (const float*)d_in[0];
    const float* ln1_g    = (const float*)d_in[1];
    const float* ln1_b    = (const float*)d_in[2];
    const float* wq       = (const float*)d_in[3];
    const float* bq       = (const float*)d_in[4];
    const float* wk       = (const float*)d_in[5];
    const float* bk       = (const float*)d_in[6];
    const float* wv       = (const float*)d_in[7];
    const float* bv       = (const float*)d_in[8];
    const float* wo       = (const float*)d_in[9];
    const float* bo       = (const float*)d_in[10];
    const float* ln2_g    = (const float*)d_in[11];
    const float* ln2_b    = (const float*)d_in[12];
    const float* router_a = (const float*)d_in[13];
    const float* router_b = (const float*)d_in[14];
    const float* re_w1    = (const float*)d_in[15];
    const float* re_b1    = (const float*)d_in[16];
    const float* re_w2    = (const float*)d_in[17];
    const float* re_b2    = (const float*)d_in[18];
    const float* se_w1    = (const float*)d_in[19];
    const float* se_b1    = (const float*)d_in[20];
    const float* se_w2    = (const float*)d_in[21];
    const float* se_b2    = (const float*)d_in[22];
    float* out = (float*)d_out;

    float *p_h1, *p_q, *p_k, *p_v, *p_attn, *p_x1, *p_h2, *p_rlat, *p_logits, *p_hs;
    cudaGetSymbolAddress((void**)&p_h1, g_h1);
    cudaGetSymbolAddress((void**)&p_q, g_q);
    cudaGetSymbolAddress((void**)&p_k, g_k);
    cudaGetSymbolAddress((void**)&p_v, g_v);
    cudaGetSymbolAddress((void**)&p_attn, g_attn);
    cudaGetSymbolAddress((void**)&p_x1, g_x1);
    cudaGetSymbolAddress((void**)&p_h2, g_h2);
    cudaGetSymbolAddress((void**)&p_rlat, g_rlat);
    cudaGetSymbolAddress((void**)&p_logits, g_logits);
    cudaGetSymbolAddress((void**)&p_hs, g_hs);

    zero_small_kernel<<<1, 32>>>();
    ln_kernel<<<TOK, 128>>>(x, ln1_g, ln1_b, p_h1);

    dim3 g512(4, 32);  // N=512 tiles x M=4096 tiles
    tgemm<0><<<g512, 256>>>(p_h1, wq, bq, nullptr, p_q, TOK, EMB, EMB);
    tgemm<0><<<g512, 256>>>(p_h1, wk, bk, nullptr, p_k, TOK, EMB, EMB);
    tgemm<0><<<g512, 256>>>(p_h1, wv, bv, nullptr, p_v, TOK, EMB, EMB);

    attn_kernel<<<dim3(32, 16), 128>>>();

    tgemm<0><<<g512, 256>>>(p_attn, wo, bo, x, p_x1, TOK, EMB, EMB);  // + residual x
    ln_kernel<<<TOK, 128>>>(p_x1, ln2_g, ln2_b, p_h2);

    // router (low-rank) — small N, fp32 path
    sgemm<0><<<dim3(1, 32), 256>>>(p_h2, router_a, nullptr, nullptr, p_rlat, TOK, RRANK, EMB);
    sgemm<0><<<dim3(1, 32), 256>>>(p_rlat, router_b, nullptr, nullptr, p_logits, TOK, NEXP, RRANK);
    router_topk_kernel<<<TOK / 128, 128>>>();
    scan_aux_kernel<<<1, 32>>>(out, out_size);
    fill_assign_kernel<<<TOK / 128, 128>>>();

    // routed experts (sparse, grouped, 3xtf32)
    routed_tgemm1<<<dim3(4, 128, 32), 256>>>(re_w1, re_b1);

    // shared expert (3xtf32)
    tgemm<1><<<dim3(32, 32), 256>>>(p_h2, se_w1, se_b1, nullptr, p_hs, TOK, SHID, EMB);
    tgemm<0><<<dim3(4, 32), 256>>>(p_hs, se_w2, se_b2, p_x1, out, TOK, EMB, SHID);

    // routed contribution accumulates on top
    routed_tgemm2<<<dim3(4, 128, 32), 256>>>(re_w2, re_b2, out);
}